// round 8
// baseline (speedup 1.0000x reference)
#include <cuda_runtime.h>
#include <cuda_bf16.h>

// Sizes (fixed): B=64, T=1024, D=512, H=256, 4H=1024, two directions.

// ---------------------------------------------------------------------------
// Scratch (device globals -- no allocation allowed)
// ---------------------------------------------------------------------------
__device__ float G_buf [(size_t)65536 * 2048];        // [m = b*1024 + t][j(0..2047)]
__device__ float Gt_buf[(size_t)1024 * 2048 * 64];    // [t][j][b]
__device__ float Hhist [(size_t)2 * 1024 * 16384];    // [dir][t][q*64 + b]
__device__ unsigned g_arrive[2][64][32];              // padded: one 128B line per (dir,slice)

// ---------------------------------------------------------------------------
// f32x2 packed-math helpers
// ---------------------------------------------------------------------------
static __device__ __forceinline__ unsigned long long pk2(float x, float y) {
    unsigned long long r;
    asm("mov.b64 %0, {%1, %2};" : "=l"(r) : "f"(x), "f"(y));
    return r;
}
static __device__ __forceinline__ unsigned long long fma2(
    unsigned long long a, unsigned long long b, unsigned long long c) {
    unsigned long long d;
    asm("fma.rn.f32x2 %0, %1, %2, %3;" : "=l"(d) : "l"(a), "l"(b), "l"(c));
    return d;
}
static __device__ __forceinline__ unsigned long long add2(
    unsigned long long a, unsigned long long b) {
    unsigned long long d;
    asm("add.rn.f32x2 %0, %1, %2;" : "=l"(d) : "l"(a), "l"(b));
    return d;
}
static __device__ __forceinline__ float2 upk(unsigned long long v) {
    float2 r;
    asm("mov.b64 {%0, %1}, %2;" : "=f"(r.x), "=f"(r.y) : "l"(v));
    return r;
}

static __device__ __forceinline__ float sigm_f(float x) {
    return __frcp_rn(1.f + __expf(-x));
}
static __device__ __forceinline__ float tanh_f(float x) {
    x = fminf(fmaxf(x, -15.f), 15.f);
    float e = __expf(2.f * x);
    return (e - 1.f) / (e + 1.f);
}

static __device__ __forceinline__ void st_rel(unsigned* p, unsigned v) {
    asm volatile("st.release.gpu.u32 [%0], %1;" :: "l"(p), "r"(v) : "memory");
}
static __device__ __forceinline__ unsigned ld_acq(const unsigned* p) {
    unsigned v;
    asm volatile("ld.acquire.gpu.u32 %0, [%1];" : "=r"(v) : "l"(p) : "memory");
    return v;
}
static __device__ __forceinline__ void cp16(void* smem_dst, const void* gsrc) {
    unsigned s = (unsigned)__cvta_generic_to_shared(smem_dst);
    asm volatile("cp.async.cg.shared.global [%0], [%1], 16;" :: "r"(s), "l"(gsrc));
}

// ---------------------------------------------------------------------------
// Reset: zero barrier state. Runs every launch.
// ---------------------------------------------------------------------------
__global__ void reset_k() {
    unsigned i = blockIdx.x * 256u + threadIdx.x;
    if (i < 4096u) (&g_arrive[0][0][0])[i] = 0u;
}

// ---------------------------------------------------------------------------
// Phase 1: G[m][j] = x[m,:] . Wih[j,:] + bih[j] + bhh[j]
// 128x128x8 tiles, 256 threads, 8x8 per-thread, f32x2 packed FMA.
// ---------------------------------------------------------------------------
__global__ void __launch_bounds__(256) gemm_in(
    const float* __restrict__ A,
    const float* __restrict__ Wf, const float* __restrict__ Wb,
    const float* __restrict__ bif, const float* __restrict__ bhf,
    const float* __restrict__ bib, const float* __restrict__ bhb)
{
    __shared__ float As[8][132];
    __shared__ float Bs[8][132];

    const int bn = blockIdx.x;          // 0..15
    const int bm = blockIdx.y;          // 0..511
    const bool fwd = (bn < 8);
    const float* Bm = fwd ? Wf : Wb;
    const int nloc = (bn & 7) * 128;

    const int tid = threadIdx.x;
    const int lr  = tid >> 1;
    const int lk  = (tid & 1) * 4;

    const float* Ap = A  + (size_t)(bm * 128 + lr) * 512 + lk;
    const float* Bp = Bm + (size_t)(nloc + lr) * 512 + lk;

    const int tx = tid & 15;
    const int ty = tid >> 4;

    unsigned long long acc[8][4];
#pragma unroll
    for (int i = 0; i < 8; i++)
#pragma unroll
        for (int j = 0; j < 4; j++) acc[i][j] = 0ull;

    float4 pa = *(const float4*)(Ap);
    float4 pb = *(const float4*)(Bp);

    for (int k0 = 0; k0 < 512; k0 += 8) {
        As[lk + 0][lr] = pa.x; As[lk + 1][lr] = pa.y;
        As[lk + 2][lr] = pa.z; As[lk + 3][lr] = pa.w;
        Bs[lk + 0][lr] = pb.x; Bs[lk + 1][lr] = pb.y;
        Bs[lk + 2][lr] = pb.z; Bs[lk + 3][lr] = pb.w;
        __syncthreads();

        if (k0 + 8 < 512) {
            pa = *(const float4*)(Ap + k0 + 8);
            pb = *(const float4*)(Bp + k0 + 8);
        }

#pragma unroll
        for (int kk = 0; kk < 8; kk++) {
            float4 a0 = *(const float4*)&As[kk][ty * 8];
            float4 a1 = *(const float4*)&As[kk][ty * 8 + 4];
            float4 b0 = *(const float4*)&Bs[kk][tx * 8];
            float4 b1 = *(const float4*)&Bs[kk][tx * 8 + 4];
            unsigned long long bb[4] = {
                pk2(b0.x, b0.y), pk2(b0.z, b0.w),
                pk2(b1.x, b1.y), pk2(b1.z, b1.w)
            };
            float av[8] = {a0.x, a0.y, a0.z, a0.w, a1.x, a1.y, a1.z, a1.w};
#pragma unroll
            for (int i = 0; i < 8; i++) {
                unsigned long long aa = pk2(av[i], av[i]);
#pragma unroll
                for (int j = 0; j < 4; j++)
                    acc[i][j] = fma2(aa, bb[j], acc[i][j]);
            }
        }
        __syncthreads();
    }

    const float* bi = fwd ? bif : bib;
    const float* bh = fwd ? bhf : bhb;
    float bias[8];
#pragma unroll
    for (int j = 0; j < 8; j++) {
        int nl = nloc + tx * 8 + j;
        bias[j] = bi[nl] + bh[nl];
    }
#pragma unroll
    for (int i = 0; i < 8; i++) {
        int m = bm * 128 + ty * 8 + i;
        float* dst = G_buf + (size_t)m * 2048 + bn * 128 + tx * 8;
        float2 c0 = upk(acc[i][0]), c1 = upk(acc[i][1]);
        float2 c2 = upk(acc[i][2]), c3 = upk(acc[i][3]);
        *(float4*)dst       = make_float4(c0.x + bias[0], c0.y + bias[1],
                                          c1.x + bias[2], c1.y + bias[3]);
        *(float4*)(dst + 4) = make_float4(c2.x + bias[4], c2.y + bias[5],
                                          c3.x + bias[6], c3.y + bias[7]);
    }
}

// ---------------------------------------------------------------------------
// Transpose G[b*1024+t][j] -> Gt[t][j][b]
// ---------------------------------------------------------------------------
__global__ void __launch_bounds__(256) transp() {
    __shared__ float tile[64][65];
    const int t  = blockIdx.y;
    const int j0 = blockIdx.x * 64;
    const int tid = threadIdx.x;

    const int jq = (tid & 15) * 4;
    const int bb = tid >> 4;
#pragma unroll
    for (int p = 0; p < 4; p++) {
        int bi = bb + p * 16;
        float4 v = *(const float4*)(G_buf + ((size_t)(bi * 1024 + t)) * 2048 + j0 + jq);
        tile[bi][jq + 0] = v.x; tile[bi][jq + 1] = v.y;
        tile[bi][jq + 2] = v.z; tile[bi][jq + 3] = v.w;
    }
    __syncthreads();

    const int bq = (tid & 15) * 4;
    const int jj = tid >> 4;
#pragma unroll
    for (int p = 0; p < 4; p++) {
        int j = jj + p * 16;
        float4 v = make_float4(tile[bq + 0][j], tile[bq + 1][j],
                               tile[bq + 2][j], tile[bq + 3][j]);
        *(float4*)(Gt_buf + ((size_t)t * 2048 + j0 + j) * 64 + bq) = v;
    }
}

// ---------------------------------------------------------------------------
// Phase 2: persistent recurrence. 128 CTAs (64 per direction), 256 threads.
// Thread = (b = tid&63, kh = tid>>6 in 0..3). Each thread computes ALL 4 q of
// the CTA's slice over its k-quarter (per k per warp: 1 h-wf + 4 w-wf for
// 8 fma2). Each kh-group cp.asyncs ONLY its own 16KB h quarter and syncs with
// a private named barrier -> staging of the four quarters overlaps.
// Cross-group reduction in smem; kh0 does activations; kh1 polls the grid
// barrier. Flat padded-flag barrier as in R7.
// ---------------------------------------------------------------------------
__global__ void __launch_bounds__(256, 1) recur(
    const float* __restrict__ Whf, const float* __restrict__ Whb)
{
    extern __shared__ float sm[];
    float* h_s = sm;                                        // [256][64] 64KB
    ulonglong2* w_s = (ulonglong2*)(sm + 16384);            // [256][4]  16KB
    unsigned long long* red = (unsigned long long*)(sm + 16384 + 4096); // [8][192] 12KB

    const int cta   = blockIdx.x;
    const int dir   = cta >> 6;
    const int slice = cta & 63;
    const int qb    = slice * 4;
    const int tid   = threadIdx.x;
    const int b     = tid & 63;
    const int kh    = tid >> 6;          // k-quarter: [64*kh, 64*kh+64)
    const bool lo   = (kh == 0);

    // Fill w_s[k][qj] = { (wi,wf), (wg,wo) } for q = qb+qj
    const float* W = dir ? Whb : Whf;
    for (int idx = tid; idx < 1024; idx += 256) {
        int k = idx >> 2, qj = idx & 3, qg = qb + qj;
        ulonglong2 v;
        v.x = pk2(W[(size_t)(      qg) * 256 + k], W[(size_t)(256 + qg) * 256 + k]);
        v.y = pk2(W[(size_t)(512 + qg) * 256 + k], W[(size_t)(768 + qg) * 256 + k]);
        w_s[idx] = v;
    }

    float c0 = 0.f, c1 = 0.f, c2 = 0.f, c3 = 0.f;

    // Gate prefetch for step 0 (kh0 only)
    int t = dir ? 1023 : 0;
    float pi[4], pf[4], pg[4], po[4];
    if (lo) {
        const float* gp = Gt_buf + ((size_t)t * 2048 + (size_t)dir * 1024) * 64 + b;
#pragma unroll
        for (int j = 0; j < 4; j++) {
            pi[j] = __ldg(gp + (size_t)(      qb + j) * 64);
            pf[j] = __ldg(gp + (size_t)(256 + qb + j) * 64);
            pg[j] = __ldg(gp + (size_t)(512 + qb + j) * 64);
            po[j] = __ldg(gp + (size_t)(768 + qb + j) * 64);
        }
    }
    __syncthreads();    // w_s ready

    float* Hd = Hhist + (size_t)dir * 1024 * 16384;
    const int bar_id = kh + 1;          // named barriers 1..4, 64 threads each

    for (int step = 0; step < 1024; ++step) {
        // Stage own 16KB h quarter (group-private) -------------------------
        float4* dstq = (float4*)h_s + kh * 1024;
        if (step == 0) {
            float4 z = make_float4(0.f, 0.f, 0.f, 0.f);
#pragma unroll
            for (int i = 0; i < 16; i++) dstq[b + i * 64] = z;
        } else {
            const int tp = dir ? (t + 1) : (t - 1);
            const float4* srcq = (const float4*)(Hd + (size_t)tp * 16384) + kh * 1024;
#pragma unroll
            for (int i = 0; i < 16; i++)
                cp16(dstq + b + i * 64, srcq + b + i * 64);
            asm volatile("cp.async.commit_group;");
            asm volatile("cp.async.wait_group 0;" ::: "memory");
        }
        asm volatile("bar.sync %0, 64;" :: "r"(bar_id) : "memory");

        // k-loop over own quarter, all 4 q ---------------------------------
        unsigned long long aif[4], ago[4];
        if (lo) {
#pragma unroll
            for (int j = 0; j < 4; j++) {
                aif[j] = pk2(pi[j], pf[j]);
                ago[j] = pk2(pg[j], po[j]);
            }
        } else {
#pragma unroll
            for (int j = 0; j < 4; j++) { aif[j] = 0ull; ago[j] = 0ull; }
        }

        const float* hq = h_s + kh * 4096 + b;
        const ulonglong2* wq = w_s + kh * 256;   // entries (kh*64+kk)*4
#pragma unroll 8
        for (int kk = 0; kk < 64; ++kk) {
            float hv = hq[kk * 64];
            unsigned long long hh = pk2(hv, hv);
#pragma unroll
            for (int j = 0; j < 4; j++) {
                ulonglong2 wv = wq[kk * 4 + j];
                aif[j] = fma2(hh, wv.x, aif[j]);
                ago[j] = fma2(hh, wv.y, ago[j]);
            }
        }

        // Publish partials (kh1..3), combine + activations (kh0) -----------
        if (!lo) {
            int base = (kh - 1) * 64 + b;       // 0..191
#pragma unroll
            for (int j = 0; j < 4; j++) {
                red[(2 * j    ) * 192 + base] = aif[j];
                red[(2 * j + 1) * 192 + base] = ago[j];
            }
        }
        __syncthreads();

        if (lo) {
#pragma unroll
            for (int j = 0; j < 4; j++) {
#pragma unroll
                for (int g = 0; g < 3; g++) {
                    aif[j] = add2(aif[j], red[(2 * j    ) * 192 + g * 64 + b]);
                    ago[j] = add2(ago[j], red[(2 * j + 1) * 192 + g * 64 + b]);
                }
            }
            float cs[4] = {c0, c1, c2, c3};
            float* hd = Hd + (size_t)t * 16384;
#pragma unroll
            for (int j = 0; j < 4; j++) {
                float2 vif = upk(aif[j]), vgo = upk(ago[j]);
                float ig = sigm_f(vif.x), fg = sigm_f(vif.y);
                float gg = tanh_f(vgo.x), og = sigm_f(vgo.y);
                cs[j] = fg * cs[j] + ig * gg;
                float hn = og * tanh_f(cs[j]);
                __stcg(hd + (qb + j) * 64 + b, hn);
            }
            c0 = cs[0]; c1 = cs[1]; c2 = cs[2]; c3 = cs[3];
        }

        if (step == 1023) break;

        // ---- arrive: push Hhist stores, signal this CTA's padded flag ----
        __threadfence();
        __syncthreads();
        if (tid == 0) st_rel(&g_arrive[dir][slice][0], (unsigned)(step + 1));

        // Hidden under the wait: next step's gate prefetch (kh0)
        t = dir ? (1022 - step) : (step + 1);
        if (lo) {
            const float* gp = Gt_buf + ((size_t)t * 2048 + (size_t)dir * 1024) * 64 + b;
#pragma unroll
            for (int j = 0; j < 4; j++) {
                pi[j] = __ldg(gp + (size_t)(      qb + j) * 64);
                pf[j] = __ldg(gp + (size_t)(256 + qb + j) * 64);
                pg[j] = __ldg(gp + (size_t)(512 + qb + j) * 64);
                po[j] = __ldg(gp + (size_t)(768 + qb + j) * 64);
            }
        }

        // ---- wait: kh1 group polls the 64 padded arrive lines ----
        if (kh == 1) {
            while (ld_acq(&g_arrive[dir][b][0]) <= (unsigned)step) {}
        }
        __syncthreads();
    }
}

// ---------------------------------------------------------------------------
// Final: out[b][t][dir*256+q] = Hhist[dir][t][q*64+b]
// ---------------------------------------------------------------------------
__global__ void __launch_bounds__(256) out_tr(float* __restrict__ out) {
    __shared__ float tile[64][65];   // [b][qq]
    const int q0  = blockIdx.x * 64;
    const int t   = blockIdx.y;
    const int dir = blockIdx.z;
    const int tid = threadIdx.x;

    const float* src = Hhist + ((size_t)dir * 1024 + t) * 16384;
    const int b  = tid & 63;
    const int q4 = (tid >> 6) * 16;
#pragma unroll
    for (int i = 0; i < 16; i++) {
        int qq = q4 + i;
        tile[b][qq] = src[(q0 + qq) * 64 + b];
    }
    __syncthreads();

    const int qs = (tid & 15) * 4;
    const int br = tid >> 4;
#pragma unroll
    for (int p = 0; p < 4; p++) {
        int bb = br + p * 16;
        float4 v = make_float4(tile[bb][qs + 0], tile[bb][qs + 1],
                               tile[bb][qs + 2], tile[bb][qs + 3]);
        *(float4*)(out + ((size_t)bb * 1024 + t) * 512 + dir * 256 + q0 + qs) = v;
    }
}

// ---------------------------------------------------------------------------
// Launch
// ---------------------------------------------------------------------------
extern "C" void kernel_launch(void* const* d_in, const int* in_sizes, int n_in,
                              void* d_out, int out_size) {
    const float* x   = (const float*)d_in[0];
    const float* Wif = (const float*)d_in[1];
    const float* Whf = (const float*)d_in[2];
    const float* bif = (const float*)d_in[3];
    const float* bhf = (const float*)d_in[4];
    const float* Wib = (const float*)d_in[5];
    const float* Whb = (const float*)d_in[6];
    const float* bib = (const float*)d_in[7];
    const float* bhb = (const float*)d_in[8];
    float* out = (float*)d_out;

    cudaFuncSetAttribute(recur, cudaFuncAttributeMaxDynamicSharedMemorySize, 94208);

    reset_k<<<16, 256>>>();
    gemm_in<<<dim3(16, 512), 256>>>(x, Wif, Wib, bif, bhf, bib, bhb);
    transp<<<dim3(32, 1024), 256>>>();
    recur<<<128, 256, 94208>>>(Whf, Whb);
    out_tr<<<dim3(4, 1024, 2), 256>>>(out);
}

// round 9
// speedup vs baseline: 1.0549x; 1.0549x over previous
#include <cuda_runtime.h>
#include <cuda_bf16.h>

// Sizes (fixed): B=64, T=1024, D=512, H=256, 4H=1024, two directions.

// ---------------------------------------------------------------------------
// Scratch (device globals -- no allocation allowed)
// ---------------------------------------------------------------------------
__device__ float G_buf [(size_t)65536 * 2048];        // [m = b*1024 + t][j(0..2047)]
__device__ float Gt_buf[(size_t)1024 * 2048 * 64];    // [t][j][b]
__device__ float Hhist [(size_t)2 * 1024 * 16384];    // [dir][t][q*64 + b]
__device__ unsigned g_arrive[2][4][16][32];           // [dir][bgroup][qslice][pad]

// ---------------------------------------------------------------------------
// f32x2 packed-math helpers
// ---------------------------------------------------------------------------
static __device__ __forceinline__ unsigned long long pk2(float x, float y) {
    unsigned long long r;
    asm("mov.b64 %0, {%1, %2};" : "=l"(r) : "f"(x), "f"(y));
    return r;
}
static __device__ __forceinline__ unsigned long long fma2(
    unsigned long long a, unsigned long long b, unsigned long long c) {
    unsigned long long d;
    asm("fma.rn.f32x2 %0, %1, %2, %3;" : "=l"(d) : "l"(a), "l"(b), "l"(c));
    return d;
}
static __device__ __forceinline__ unsigned long long add2(
    unsigned long long a, unsigned long long b) {
    unsigned long long d;
    asm("add.rn.f32x2 %0, %1, %2;" : "=l"(d) : "l"(a), "l"(b));
    return d;
}
static __device__ __forceinline__ float2 upk(unsigned long long v) {
    float2 r;
    asm("mov.b64 {%0, %1}, %2;" : "=f"(r.x), "=f"(r.y) : "l"(v));
    return r;
}

static __device__ __forceinline__ float sigm_f(float x) {
    return __frcp_rn(1.f + __expf(-x));
}
static __device__ __forceinline__ float tanh_f(float x) {
    x = fminf(fmaxf(x, -15.f), 15.f);
    float e = __expf(2.f * x);
    return (e - 1.f) / (e + 1.f);
}

static __device__ __forceinline__ void st_rel(unsigned* p, unsigned v) {
    asm volatile("st.release.gpu.u32 [%0], %1;" :: "l"(p), "r"(v) : "memory");
}
static __device__ __forceinline__ unsigned ld_acq(const unsigned* p) {
    unsigned v;
    asm volatile("ld.acquire.gpu.u32 %0, [%1];" : "=r"(v) : "l"(p) : "memory");
    return v;
}
static __device__ __forceinline__ void cp16(void* smem_dst, const void* gsrc) {
    unsigned s = (unsigned)__cvta_generic_to_shared(smem_dst);
    asm volatile("cp.async.cg.shared.global [%0], [%1], 16;" :: "r"(s), "l"(gsrc));
}

// ---------------------------------------------------------------------------
// Reset: zero barrier state. Runs every launch.
// ---------------------------------------------------------------------------
__global__ void reset_k() {
    unsigned i = blockIdx.x * 256u + threadIdx.x;
    if (i < 4096u) (&g_arrive[0][0][0][0])[i] = 0u;
}

// ---------------------------------------------------------------------------
// Phase 1: G[m][j] = x[m,:] . Wih[j,:] + bih[j] + bhh[j]
// 128x128x8 tiles, 256 threads, 8x8 per-thread, f32x2 packed FMA.
// ---------------------------------------------------------------------------
__global__ void __launch_bounds__(256) gemm_in(
    const float* __restrict__ A,
    const float* __restrict__ Wf, const float* __restrict__ Wb,
    const float* __restrict__ bif, const float* __restrict__ bhf,
    const float* __restrict__ bib, const float* __restrict__ bhb)
{
    __shared__ float As[8][132];
    __shared__ float Bs[8][132];

    const int bn = blockIdx.x;          // 0..15
    const int bm = blockIdx.y;          // 0..511
    const bool fwd = (bn < 8);
    const float* Bm = fwd ? Wf : Wb;
    const int nloc = (bn & 7) * 128;

    const int tid = threadIdx.x;
    const int lr  = tid >> 1;
    const int lk  = (tid & 1) * 4;

    const float* Ap = A  + (size_t)(bm * 128 + lr) * 512 + lk;
    const float* Bp = Bm + (size_t)(nloc + lr) * 512 + lk;

    const int tx = tid & 15;
    const int ty = tid >> 4;

    unsigned long long acc[8][4];
#pragma unroll
    for (int i = 0; i < 8; i++)
#pragma unroll
        for (int j = 0; j < 4; j++) acc[i][j] = 0ull;

    float4 pa = *(const float4*)(Ap);
    float4 pb = *(const float4*)(Bp);

    for (int k0 = 0; k0 < 512; k0 += 8) {
        As[lk + 0][lr] = pa.x; As[lk + 1][lr] = pa.y;
        As[lk + 2][lr] = pa.z; As[lk + 3][lr] = pa.w;
        Bs[lk + 0][lr] = pb.x; Bs[lk + 1][lr] = pb.y;
        Bs[lk + 2][lr] = pb.z; Bs[lk + 3][lr] = pb.w;
        __syncthreads();

        if (k0 + 8 < 512) {
            pa = *(const float4*)(Ap + k0 + 8);
            pb = *(const float4*)(Bp + k0 + 8);
        }

#pragma unroll
        for (int kk = 0; kk < 8; kk++) {
            float4 a0 = *(const float4*)&As[kk][ty * 8];
            float4 a1 = *(const float4*)&As[kk][ty * 8 + 4];
            float4 b0 = *(const float4*)&Bs[kk][tx * 8];
            float4 b1 = *(const float4*)&Bs[kk][tx * 8 + 4];
            unsigned long long bb[4] = {
                pk2(b0.x, b0.y), pk2(b0.z, b0.w),
                pk2(b1.x, b1.y), pk2(b1.z, b1.w)
            };
            float av[8] = {a0.x, a0.y, a0.z, a0.w, a1.x, a1.y, a1.z, a1.w};
#pragma unroll
            for (int i = 0; i < 8; i++) {
                unsigned long long aa = pk2(av[i], av[i]);
#pragma unroll
                for (int j = 0; j < 4; j++)
                    acc[i][j] = fma2(aa, bb[j], acc[i][j]);
            }
        }
        __syncthreads();
    }

    const float* bi = fwd ? bif : bib;
    const float* bh = fwd ? bhf : bhb;
    float bias[8];
#pragma unroll
    for (int j = 0; j < 8; j++) {
        int nl = nloc + tx * 8 + j;
        bias[j] = bi[nl] + bh[nl];
    }
#pragma unroll
    for (int i = 0; i < 8; i++) {
        int m = bm * 128 + ty * 8 + i;
        float* dst = G_buf + (size_t)m * 2048 + bn * 128 + tx * 8;
        float2 c0 = upk(acc[i][0]), c1 = upk(acc[i][1]);
        float2 c2 = upk(acc[i][2]), c3 = upk(acc[i][3]);
        *(float4*)dst       = make_float4(c0.x + bias[0], c0.y + bias[1],
                                          c1.x + bias[2], c1.y + bias[3]);
        *(float4*)(dst + 4) = make_float4(c2.x + bias[4], c2.y + bias[5],
                                          c3.x + bias[6], c3.y + bias[7]);
    }
}

// ---------------------------------------------------------------------------
// Transpose G[b*1024+t][j] -> Gt[t][j][b]
// ---------------------------------------------------------------------------
__global__ void __launch_bounds__(256) transp() {
    __shared__ float tile[64][65];
    const int t  = blockIdx.y;
    const int j0 = blockIdx.x * 64;
    const int tid = threadIdx.x;

    const int jq = (tid & 15) * 4;
    const int bb = tid >> 4;
#pragma unroll
    for (int p = 0; p < 4; p++) {
        int bi = bb + p * 16;
        float4 v = *(const float4*)(G_buf + ((size_t)(bi * 1024 + t)) * 2048 + j0 + jq);
        tile[bi][jq + 0] = v.x; tile[bi][jq + 1] = v.y;
        tile[bi][jq + 2] = v.z; tile[bi][jq + 3] = v.w;
    }
    __syncthreads();

    const int bq = (tid & 15) * 4;
    const int jj = tid >> 4;
#pragma unroll
    for (int p = 0; p < 4; p++) {
        int j = jj + p * 16;
        float4 v = make_float4(tile[bq + 0][j], tile[bq + 1][j],
                               tile[bq + 2][j], tile[bq + 3][j]);
        *(float4*)(Gt_buf + ((size_t)t * 2048 + j0 + j) * 64 + bq) = v;
    }
}

// ---------------------------------------------------------------------------
// Phase 2: persistent recurrence. 128 CTAs, 256 threads.
// CTA = (dir, bg 0..3, qs 0..15): owns q in [qs*16, qs*16+16) x b in
// [bg*16, bg*16+16). The recurrence is independent per b, so CTAs only sync
// within their (dir,bg) group of 16 -> 4x fewer barrier arrivals, 4x smaller
// h exchange (16KB/CTA/step).
// Thread = (b = tid&15, qq = (tid>>4)&3 owning 4 q, kh = tid>>6 k-quarter).
// ---------------------------------------------------------------------------
__global__ void __launch_bounds__(256, 1) recur(
    const float* __restrict__ Whf, const float* __restrict__ Whb)
{
    extern __shared__ float sm[];
    float* h_s = sm;                                     // [256 k][16 b] 16KB
    ulonglong2* w_s = (ulonglong2*)(sm + 4096);          // [16 q][256 k] 64KB
    unsigned long long* red = (unsigned long long*)(sm + 4096 + 16384); // 12KB

    const int cta = blockIdx.x;
    const int dir = cta >> 6;
    const int grp = cta & 63;
    const int bg  = grp >> 4;           // b-group 0..3
    const int qs  = grp & 15;           // q-slice 0..15
    const int b0  = bg * 16;
    const int qb  = qs * 16;            // global q base of this slice
    const int tid = threadIdx.x;
    const int b   = tid & 15;           // local b
    const int qq  = (tid >> 4) & 3;     // q-quad within slice
    const int kh  = tid >> 6;           // k-quarter
    const bool lo = (kh == 0);
    const int bglob = b0 + b;

    // Fill w_s[q_loc*256 + k] = { (wi,wf), (wg,wo) } for q = qb + q_loc
    const float* W = dir ? Whb : Whf;
    for (int idx = tid; idx < 4096; idx += 256) {
        int q_loc = idx >> 8;
        int k     = idx & 255;
        int qg    = qb + q_loc;
        ulonglong2 v;
        v.x = pk2(W[(size_t)(      qg) * 256 + k], W[(size_t)(256 + qg) * 256 + k]);
        v.y = pk2(W[(size_t)(512 + qg) * 256 + k], W[(size_t)(768 + qg) * 256 + k]);
        w_s[idx] = v;
    }

    float cs[4] = {0.f, 0.f, 0.f, 0.f};

    // Gate prefetch for step 0 (kh0 only); thread's 4 q: qb + qq*4 + j
    int t = dir ? 1023 : 0;
    float pi[4], pf[4], pg[4], po[4];
    if (lo) {
        const float* gp = Gt_buf + ((size_t)t * 2048 + (size_t)dir * 1024) * 64 + bglob;
#pragma unroll
        for (int j = 0; j < 4; j++) {
            int qg = qb + qq * 4 + j;
            pi[j] = __ldg(gp + (size_t)(      qg) * 64);
            pf[j] = __ldg(gp + (size_t)(256 + qg) * 64);
            pg[j] = __ldg(gp + (size_t)(512 + qg) * 64);
            po[j] = __ldg(gp + (size_t)(768 + qg) * 64);
        }
    }
    __syncthreads();    // w_s ready

    float* Hd = Hhist + (size_t)dir * 1024 * 16384;
    const int bar_id = kh + 1;          // named barriers 1..4, 64 threads each
    const int lcl = tid & 63;           // id within kh group

    for (int step = 0; step < 1024; ++step) {
        // Stage own k-quarter x 16 b (4KB) -- group-private ----------------
        float4* dstq = (float4*)h_s + kh * 256;
        if (step == 0) {
            float4 z = make_float4(0.f, 0.f, 0.f, 0.f);
#pragma unroll
            for (int i = 0; i < 4; i++) dstq[lcl + i * 64] = z;
        } else {
            const int tp = dir ? (t + 1) : (t - 1);
            const float4* srcb = (const float4*)(Hd + (size_t)tp * 16384);
#pragma unroll
            for (int i = 0; i < 4; i++) {
                int idx = lcl + i * 64;              // 0..255 in quarter
                int kl  = idx >> 2;                  // k within quarter
                int c   = idx & 3;                   // b-chunk of 4
                cp16(dstq + idx, srcb + (size_t)(kh * 64 + kl) * 16 + (b0 >> 2) + c);
            }
            asm volatile("cp.async.commit_group;");
            asm volatile("cp.async.wait_group 0;" ::: "memory");
        }
        asm volatile("bar.sync %0, 64;" :: "r"(bar_id) : "memory");

        // k-loop over own quarter, this thread's 4 q -----------------------
        unsigned long long aif[4], ago[4];
        if (lo) {
#pragma unroll
            for (int j = 0; j < 4; j++) {
                aif[j] = pk2(pi[j], pf[j]);
                ago[j] = pk2(pg[j], po[j]);
            }
        } else {
#pragma unroll
            for (int j = 0; j < 4; j++) { aif[j] = 0ull; ago[j] = 0ull; }
        }

        const float* hq = h_s + kh * 64 * 16 + b;            // stride 16 over k
        const ulonglong2* wq = w_s + (qq * 4) * 256 + kh * 64;
#pragma unroll 8
        for (int kk = 0; kk < 64; ++kk) {
            float hv = hq[kk * 16];
            unsigned long long hh = pk2(hv, hv);
#pragma unroll
            for (int j = 0; j < 4; j++) {
                ulonglong2 wv = wq[j * 256 + kk];
                aif[j] = fma2(hh, wv.x, aif[j]);
                ago[j] = fma2(hh, wv.y, ago[j]);
            }
        }

        // Publish partials (kh1..3), combine + activations (kh0) -----------
        if (!lo) {
            int base = (kh - 1) * 64 + lcl;         // 0..191
#pragma unroll
            for (int j = 0; j < 4; j++) {
                red[(2 * j    ) * 192 + base] = aif[j];
                red[(2 * j + 1) * 192 + base] = ago[j];
            }
        }
        __syncthreads();

        if (lo) {
#pragma unroll
            for (int j = 0; j < 4; j++) {
#pragma unroll
                for (int g = 0; g < 3; g++) {
                    aif[j] = add2(aif[j], red[(2 * j    ) * 192 + g * 64 + tid]);
                    ago[j] = add2(ago[j], red[(2 * j + 1) * 192 + g * 64 + tid]);
                }
            }
            float* hd = Hd + (size_t)t * 16384;
#pragma unroll
            for (int j = 0; j < 4; j++) {
                float2 vif = upk(aif[j]), vgo = upk(ago[j]);
                float ig = sigm_f(vif.x), fg = sigm_f(vif.y);
                float gg = tanh_f(vgo.x), og = sigm_f(vgo.y);
                cs[j] = fg * cs[j] + ig * gg;
                float hn = og * tanh_f(cs[j]);
                __stcg(hd + (qb + qq * 4 + j) * 64 + bglob, hn);
            }
        }

        if (step == 1023) break;

        // ---- arrive: push Hhist stores, signal this CTA's padded flag ----
        __threadfence();
        __syncthreads();
        if (tid == 0) st_rel(&g_arrive[dir][bg][qs][0], (unsigned)(step + 1));

        // Hidden under the wait: next step's gate prefetch (kh0)
        t = dir ? (1022 - step) : (step + 1);
        if (lo) {
            const float* gp = Gt_buf + ((size_t)t * 2048 + (size_t)dir * 1024) * 64 + bglob;
#pragma unroll
            for (int j = 0; j < 4; j++) {
                int qg = qb + qq * 4 + j;
                pi[j] = __ldg(gp + (size_t)(      qg) * 64);
                pf[j] = __ldg(gp + (size_t)(256 + qg) * 64);
                pg[j] = __ldg(gp + (size_t)(512 + qg) * 64);
                po[j] = __ldg(gp + (size_t)(768 + qg) * 64);
            }
        }

        // ---- wait: kh1 group polls the 16 padded arrive lines of (dir,bg)
        if (kh == 1 && lcl < 16) {
            while (ld_acq(&g_arrive[dir][bg][lcl][0]) <= (unsigned)step) {}
        }
        __syncthreads();
    }
}

// ---------------------------------------------------------------------------
// Final: out[b][t][dir*256+q] = Hhist[dir][t][q*64+b]
// ---------------------------------------------------------------------------
__global__ void __launch_bounds__(256) out_tr(float* __restrict__ out) {
    __shared__ float tile[64][65];   // [b][qq]
    const int q0  = blockIdx.x * 64;
    const int t   = blockIdx.y;
    const int dir = blockIdx.z;
    const int tid = threadIdx.x;

    const float* src = Hhist + ((size_t)dir * 1024 + t) * 16384;
    const int b  = tid & 63;
    const int q4 = (tid >> 6) * 16;
#pragma unroll
    for (int i = 0; i < 16; i++) {
        int qq = q4 + i;
        tile[b][qq] = src[(q0 + qq) * 64 + b];
    }
    __syncthreads();

    const int qs = (tid & 15) * 4;
    const int br = tid >> 4;
#pragma unroll
    for (int p = 0; p < 4; p++) {
        int bb = br + p * 16;
        float4 v = make_float4(tile[bb][qs + 0], tile[bb][qs + 1],
                               tile[bb][qs + 2], tile[bb][qs + 3]);
        *(float4*)(out + ((size_t)bb * 1024 + t) * 512 + dir * 256 + q0 + qs) = v;
    }
}

// ---------------------------------------------------------------------------
// Launch
// ---------------------------------------------------------------------------
extern "C" void kernel_launch(void* const* d_in, const int* in_sizes, int n_in,
                              void* d_out, int out_size) {
    const float* x   = (const float*)d_in[0];
    const float* Wif = (const float*)d_in[1];
    const float* Whf = (const float*)d_in[2];
    const float* bif = (const float*)d_in[3];
    const float* bhf = (const float*)d_in[4];
    const float* Wib = (const float*)d_in[5];
    const float* Whb = (const float*)d_in[6];
    const float* bib = (const float*)d_in[7];
    const float* bhb = (const float*)d_in[8];
    float* out = (float*)d_out;

    cudaFuncSetAttribute(recur, cudaFuncAttributeMaxDynamicSharedMemorySize, 94208);

    reset_k<<<16, 256>>>();
    gemm_in<<<dim3(16, 512), 256>>>(x, Wif, Wib, bif, bhf, bib, bhb);
    transp<<<dim3(32, 1024), 256>>>();
    recur<<<128, 256, 94208>>>(Whf, Whb);
    out_tr<<<dim3(4, 1024, 2), 256>>>(out);
}